// round 1
// baseline (speedup 1.0000x reference)
#include <cuda_runtime.h>
#include <math.h>
#include <float.h>

// ---------------------------------------------------------------------------
// VectorQuantizerEMA on GB300/B200-class sm_10x
//
// distances = ||x||^2 + ||e||^2 - 2 x.e^T ; argmin over 8192 codes.
// GEMM done as 3xTF32 split (error ~ fp32) via mma.sync.m16n8k8.tf32:
//   A' = [A_hi | A_hi | A_lo]  (32768 x 1536)
//   B' = [B_hi | B_lo | B_hi]  ( 8192 x 1536)
//   score = B'.A'^T contributions = hi*hi + hi*lo + lo*hi
// ---------------------------------------------------------------------------

#define NUM_IN   32768
#define NUM_CODE 8192
#define DIM      512
#define KP       1536                     // 3*DIM
#define NCHUNK   4
#define CODES_PER_CHUNK (NUM_CODE/NCHUNK) // 2048
#define BM 128
#define BN 128
#define BK 32
#define KSTAGES (KP/BK)                   // 48
#define NTILES  (CODES_PER_CHUNK/BN)      // 16
#define SROW 36                           // padded words per smem row (conflict-free)
#define STAGE_F (BM*SROW)                 // 4608 floats per tile stage

// output layout (flattened reference return tuple, fp32)
#define O_Q    0
#define O_LOSS 16777216
#define O_PERP 16777217
#define O_EMB  16777218
#define O_CS   20971522
#define O_W    20979714

#define SMEM_BYTES ((4*STAGE_F + 128 + 128 + 128) * 4)

// ------------------------------- scratch -----------------------------------
__device__ float  g_Ap[(size_t)NUM_IN * KP];    // 192 MB
__device__ float  g_Bp[(size_t)NUM_CODE * KP];  // 48 MB
__device__ float  g_bnorm[NUM_CODE];
__device__ float  g_cand_val[NCHUNK][NUM_IN];
__device__ int    g_cand_idx[NCHUNK][NUM_IN];
__device__ int    g_best[NUM_IN];
__device__ float  g_counts[NUM_CODE];
__device__ double g_loss_sum;

// ------------------------------- helpers -----------------------------------
__device__ __forceinline__ float f2tf32(float x) {
    unsigned u;
    asm("cvt.rna.tf32.f32 %0, %1;" : "=r"(u) : "f"(x));
    return __uint_as_float(u);
}

__device__ __forceinline__ unsigned smem_u32(const void* p) {
    return (unsigned)__cvta_generic_to_shared(p);
}

__device__ __forceinline__ void cp16(unsigned s, const void* g) {
    asm volatile("cp.async.cg.shared.global [%0], [%1], 16;\n" :: "r"(s), "l"(g) : "memory");
}
__device__ __forceinline__ void cp_commit() {
    asm volatile("cp.async.commit_group;\n" ::: "memory");
}
template <int N>
__device__ __forceinline__ void cp_wait() {
    asm volatile("cp.async.wait_group %0;\n" :: "n"(N) : "memory");
}

__device__ __forceinline__ void mma_tf32(float* d, const unsigned* a, const unsigned* b) {
    asm volatile(
        "mma.sync.aligned.m16n8k8.row.col.f32.tf32.tf32.f32 "
        "{%0,%1,%2,%3}, {%4,%5,%6,%7}, {%8,%9}, {%0,%1,%2,%3};\n"
        : "+f"(d[0]), "+f"(d[1]), "+f"(d[2]), "+f"(d[3])
        : "r"(a[0]), "r"(a[1]), "r"(a[2]), "r"(a[3]), "r"(b[0]), "r"(b[1]));
}

// ------------------------------ small kernels -------------------------------
__global__ void k_zero() {
    int i = blockIdx.x * blockDim.x + threadIdx.x;
    if (i < NUM_CODE) g_counts[i] = 0.0f;
    if (i == 0) g_loss_sum = 0.0;
}

__global__ void k_init_w(const float* __restrict__ ema_w, float* __restrict__ out) {
    for (long i = (long)blockIdx.x * blockDim.x + threadIdx.x;
         i < (long)NUM_CODE * DIM; i += (long)gridDim.x * blockDim.x)
        out[O_W + i] = 0.99f * ema_w[i];
}

__global__ void k_prep_a(const float* __restrict__ X) {
    for (long i = (long)blockIdx.x * blockDim.x + threadIdx.x;
         i < (long)NUM_IN * DIM; i += (long)gridDim.x * blockDim.x) {
        int m = (int)(i >> 9);
        int j = (int)(i & 511);
        float v = X[i];
        float hi = f2tf32(v);
        float lo = v - hi;
        float* row = g_Ap + (size_t)m * KP;
        row[j]        = hi;   // seg0 pairs with B_hi
        row[512 + j]  = hi;   // seg1 pairs with B_lo
        row[1024 + j] = lo;   // seg2 pairs with B_hi
    }
}

__global__ void k_prep_b(const float* __restrict__ E) {
    int k = blockIdx.x;
    int t = threadIdx.x;           // 128 threads
    const float* er = E + (size_t)k * DIM;
    float* br = g_Bp + (size_t)k * KP;
    float s = 0.0f;
    for (int j = t; j < DIM; j += 128) {
        float v = er[j];
        float hi = f2tf32(v);
        float lo = v - hi;
        br[j]        = hi;
        br[512 + j]  = lo;
        br[1024 + j] = hi;
        s += v * v;
    }
    // block reduce (4 warps)
    for (int o = 16; o > 0; o >>= 1) s += __shfl_down_sync(0xffffffffu, s, o);
    __shared__ float sw[4];
    if ((t & 31) == 0) sw[t >> 5] = s;
    __syncthreads();
    if (t == 0) g_bnorm[k] = sw[0] + sw[1] + sw[2] + sw[3];
}

// ------------------------------ main GEMM+argmin ----------------------------
__device__ __forceinline__ void load_stage(float* As, float* Bs,
                                           const float* Ag, const float* Bg,
                                           int kbase, int tid) {
#pragma unroll
    for (int i = 0; i < 4; i++) {
        int l = tid + 256 * i;
        int r = l >> 3, f = l & 7;
        cp16(smem_u32(As + r * SROW + f * 4), Ag + (size_t)r * KP + kbase + f * 4);
    }
#pragma unroll
    for (int i = 0; i < 4; i++) {
        int l = tid + 256 * i;
        int r = l >> 3, f = l & 7;
        cp16(smem_u32(Bs + r * SROW + f * 4), Bg + (size_t)r * KP + kbase + f * 4);
    }
}

extern __shared__ float smem[];

__global__ void __launch_bounds__(256, 2) k_argmin_gemm() {
    float* As0   = smem;                    // 2 stages of A
    float* Bs0   = smem + 2 * STAGE_F;      // 2 stages of B
    float* sbias = smem + 4 * STAGE_F;      // 128
    float* rval  = sbias + 128;             // 128
    int*   ridx  = (int*)(rval + 128);      // 128

    const int tid   = threadIdx.x;
    const int lane  = tid & 31;
    const int warp  = tid >> 5;
    const int warpM = warp & 3;   // 0..3
    const int warpN = warp >> 2;  // 0..1
    const int g     = lane >> 2;  // 0..7
    const int q     = lane & 3;   // 0..3

    const int chunk = blockIdx.x;  // 0..3
    const int mtile = blockIdx.y;  // 0..255

    const float* Apanel = g_Ap + (size_t)mtile * BM * KP;

    float bestv[4];
    int   besti[4];
#pragma unroll
    for (int s = 0; s < 4; s++) { bestv[s] = FLT_MAX; besti[s] = 0x7fffffff; }

    for (int nt = 0; nt < NTILES; ++nt) {
        const int code0 = chunk * CODES_PER_CHUNK + nt * BN;
        const float* Bpanel = g_Bp + (size_t)code0 * KP;

        if (tid < 128) sbias[tid] = g_bnorm[code0 + tid];

        float acc[2][8][4];
#pragma unroll
        for (int m = 0; m < 2; m++)
#pragma unroll
            for (int j = 0; j < 8; j++)
#pragma unroll
                for (int c = 0; c < 4; c++) acc[m][j][c] = 0.0f;

        // prime pipeline
        load_stage(As0, Bs0 + 0, Apanel, Bpanel, 0, tid);
        // note: Bs0 base already offset; stage 0 of B is Bs0[0..STAGE_F)
        cp_commit();

        for (int ks = 0; ks < KSTAGES; ++ks) {
            const int buf = ks & 1;
            if (ks + 1 < KSTAGES) {
                load_stage(As0 + (buf ^ 1) * STAGE_F, Bs0 + (buf ^ 1) * STAGE_F,
                           Apanel, Bpanel, (ks + 1) * BK, tid);
                cp_commit();
                cp_wait<1>();
            } else {
                cp_wait<0>();
            }
            __syncthreads();

            const float* As = As0 + buf * STAGE_F;
            const float* Bs = Bs0 + buf * STAGE_F;
            const float* ApT = As + (warpM * 32 + g) * SROW + q;
            const float* BpT = Bs + (warpN * 64 + g) * SROW + q;

#pragma unroll
            for (int kk = 0; kk < 4; ++kk) {
                const int ko = kk * 8;
                unsigned a[2][4], b[8][2];
#pragma unroll
                for (int m = 0; m < 2; m++) {
                    const float* p = ApT + m * 16 * SROW + ko;
                    a[m][0] = __float_as_uint(p[0]);
                    a[m][1] = __float_as_uint(p[8 * SROW]);
                    a[m][2] = __float_as_uint(p[4]);
                    a[m][3] = __float_as_uint(p[8 * SROW + 4]);
                }
#pragma unroll
                for (int j = 0; j < 8; j++) {
                    const float* p = BpT + j * 8 * SROW + ko;
                    b[j][0] = __float_as_uint(p[0]);
                    b[j][1] = __float_as_uint(p[4]);
                }
#pragma unroll
                for (int m = 0; m < 2; m++)
#pragma unroll
                    for (int j = 0; j < 8; j++)
                        mma_tf32(acc[m][j], a[m], b[j]);
            }
            __syncthreads();
        }

        // ---- epilogue: scores = bias - 2*dot, running argmin ----
        const int codeg0 = code0;  // global code id base of this 128-wide tile
#pragma unroll
        for (int m = 0; m < 2; m++) {
#pragma unroll
            for (int half = 0; half < 2; half++) {
                const int slot = m * 2 + half;
                float v = FLT_MAX;
                int   vi = 0x7fffffff;
#pragma unroll
                for (int j = 0; j < 8; j++) {
                    const int colb = warpN * 64 + j * 8 + 2 * q;
                    const float s0 = sbias[colb]     - 2.0f * acc[m][j][half * 2 + 0];
                    const float s1 = sbias[colb + 1] - 2.0f * acc[m][j][half * 2 + 1];
                    const int c0 = codeg0 + colb;
                    if (s0 < v || (s0 == v && c0 < vi))     { v = s0; vi = c0; }
                    if (s1 < v || (s1 == v && c0 + 1 < vi)) { v = s1; vi = c0 + 1; }
                }
                // quad reduce (lanes sharing rows, cols partitioned by q)
#pragma unroll
                for (int off = 1; off < 4; off <<= 1) {
                    float ov = __shfl_xor_sync(0xffffffffu, v, off);
                    int   oi = __shfl_xor_sync(0xffffffffu, vi, off);
                    if (ov < v || (ov == v && oi < vi)) { v = ov; vi = oi; }
                }
                if (v < bestv[slot] || (v == bestv[slot] && vi < besti[slot])) {
                    bestv[slot] = v; besti[slot] = vi;
                }
            }
        }
        __syncthreads();  // protect sbias before next tile rewrites it
    }

    // ---- cross-warp (warpN pair) combine and write candidates ----
    if (warpN == 1 && q == 0) {
#pragma unroll
        for (int s = 0; s < 4; s++) {
            const int m = s >> 1, half = s & 1;
            const int row = warpM * 32 + m * 16 + half * 8 + g;
            rval[row] = bestv[s];
            ridx[row] = besti[s];
        }
    }
    __syncthreads();
    if (warpN == 0 && q == 0) {
#pragma unroll
        for (int s = 0; s < 4; s++) {
            const int m = s >> 1, half = s & 1;
            const int row = warpM * 32 + m * 16 + half * 8 + g;
            float v = bestv[s]; int vi = besti[s];
            float ov = rval[row]; int oi = ridx[row];
            if (ov < v || (ov == v && oi < vi)) { v = ov; vi = oi; }
            g_cand_val[chunk][mtile * 128 + row] = v;
            g_cand_idx[chunk][mtile * 128 + row] = vi;
        }
    }
}

__global__ void k_combine() {
    int r = blockIdx.x * blockDim.x + threadIdx.x;
    if (r >= NUM_IN) return;
    float v = g_cand_val[0][r];
    int vi = g_cand_idx[0][r];
#pragma unroll
    for (int c = 1; c < NCHUNK; c++) {
        float ov = g_cand_val[c][r];
        int oi = g_cand_idx[c][r];
        if (ov < v || (ov == v && oi < vi)) { v = ov; vi = oi; }
    }
    g_best[r] = vi;
}

// ----------------------- gather + scatter (EMA stats) -----------------------
__global__ void k_gather(const float* __restrict__ X, const float* __restrict__ E,
                         float* __restrict__ out) {
    const int row = blockIdx.x;
    const int t = threadIdx.x;  // 128 threads, one float4 each (512 floats/row)
    const int k = g_best[row];

    const float4* ev = (const float4*)(E + (size_t)k * DIM);
    const float4* xv = (const float4*)(X + (size_t)row * DIM);
    float4* qv = (float4*)(out + O_Q + (size_t)row * DIM);
    float* wv = out + O_W + (size_t)k * DIM;

    float4 e4 = __ldg(ev + t);
    float4 x4 = __ldg(xv + t);
    qv[t] = e4;  // quantized_st == quantized numerically

    float dx = e4.x - x4.x, dy = e4.y - x4.y, dz = e4.z - x4.z, dw = e4.w - x4.w;
    float ls = dx * dx + dy * dy + dz * dz + dw * dw;

    atomicAdd(wv + 4 * t + 0, 0.01f * x4.x);
    atomicAdd(wv + 4 * t + 1, 0.01f * x4.y);
    atomicAdd(wv + 4 * t + 2, 0.01f * x4.z);
    atomicAdd(wv + 4 * t + 3, 0.01f * x4.w);

    for (int o = 16; o > 0; o >>= 1) ls += __shfl_down_sync(0xffffffffu, ls, o);
    __shared__ float sred[4];
    if ((t & 31) == 0) sred[t >> 5] = ls;
    __syncthreads();
    if (t == 0) {
        float tot = sred[0] + sred[1] + sred[2] + sred[3];
        atomicAdd(&g_loss_sum, (double)tot);
        atomicAdd(&g_counts[k], 1.0f);
    }
}

// ----------------------------- finalize -------------------------------------
__global__ void k_finalize(const float* __restrict__ cs_in, float* __restrict__ out) {
    __shared__ float  spre[NUM_CODE];  // 32 KB
    __shared__ double snd[256];
    __shared__ float  shd[256];
    const int t = threadIdx.x;  // 256
    double nl = 0.0;
    float hl = 0.0f;
    for (int k = t; k < NUM_CODE; k += 256) {
        float c = g_counts[k];
        float pre = 0.99f * cs_in[k] + 0.01f * c;
        spre[k] = pre;
        nl += (double)pre;
        float p = c * (1.0f / 32768.0f);
        hl += p * logf(p + 1e-10f);
    }
    snd[t] = nl; shd[t] = hl;
    __syncthreads();
    for (int s = 128; s > 0; s >>= 1) {
        if (t < s) { snd[t] += snd[t + s]; shd[t] += shd[t + s]; }
        __syncthreads();
    }
    const float n = (float)snd[0];
    const float denom = n + (float)NUM_CODE * 1e-5f;
    for (int k = t; k < NUM_CODE; k += 256)
        out[O_CS + k] = (spre[k] + 1e-5f) / denom * n;
    if (t == 0) {
        out[O_LOSS] = 0.25f * (float)(g_loss_sum / 16777216.0);
        out[O_PERP] = expf(-shd[0]);
    }
}

__global__ void k_newemb(float* __restrict__ out) {
    for (long i = (long)blockIdx.x * blockDim.x + threadIdx.x;
         i < (long)NUM_CODE * DIM; i += (long)gridDim.x * blockDim.x)
        out[O_EMB + i] = out[O_W + i] / out[O_CS + (i >> 9)];
}

// ------------------------------- launch --------------------------------------
extern "C" void kernel_launch(void* const* d_in, const int* in_sizes, int n_in,
                              void* d_out, int out_size) {
    const float* X  = (const float*)d_in[0];  // inputs          [32768,512]
    const float* E  = (const float*)d_in[1];  // embedding       [8192,512]
    const float* CS = (const float*)d_in[2];  // ema_cluster_size[8192]
    const float* W  = (const float*)d_in[3];  // ema_w           [8192,512]
    float* out = (float*)d_out;

    cudaFuncSetAttribute(k_argmin_gemm, cudaFuncAttributeMaxDynamicSharedMemorySize,
                         SMEM_BYTES);

    k_zero<<<(NUM_CODE + 255) / 256, 256>>>();
    k_init_w<<<4096, 256>>>(W, out);
    k_prep_b<<<NUM_CODE, 128>>>(E);
    k_prep_a<<<8192, 256>>>(X);
    k_argmin_gemm<<<dim3(NCHUNK, NUM_IN / BM), 256, SMEM_BYTES>>>();
    k_combine<<<NUM_IN / 256, 256>>>();
    k_gather<<<NUM_IN, 128>>>(X, E, out);
    k_finalize<<<1, 256>>>(CS, out);
    k_newemb<<<4096, 256>>>(out);
}

// round 2
// speedup vs baseline: 1.0016x; 1.0016x over previous
#include <cuda_runtime.h>
#include <math.h>
#include <float.h>

// ---------------------------------------------------------------------------
// VectorQuantizerEMA on GB300/B200-class sm_10x
//
// distances = ||x||^2 + ||e||^2 - 2 x.e^T ; argmin over 8192 codes.
// GEMM done as 3xTF32 split (error ~ fp32) via mma.sync.m16n8k8.tf32:
//   A' = [A_hi | A_hi | A_lo]  (32768 x 1536)
//   B' = [B_hi | B_lo | B_hi]  ( 8192 x 1536)
//   score = B'.A'^T contributions = hi*hi + hi*lo + lo*hi
// ---------------------------------------------------------------------------

#define NUM_IN   32768
#define NUM_CODE 8192
#define DIM      512
#define KP       1536                     // 3*DIM
#define NCHUNK   4
#define CODES_PER_CHUNK (NUM_CODE/NCHUNK) // 2048
#define BM 128
#define BN 128
#define BK 32
#define KSTAGES (KP/BK)                   // 48
#define NTILES  (CODES_PER_CHUNK/BN)      // 16
#define SROW 36                           // padded words per smem row (conflict-free)
#define STAGE_F (BM*SROW)                 // 4608 floats per tile stage

// output layout (flattened reference return tuple, fp32)
#define O_Q    0
#define O_LOSS 16777216
#define O_PERP 16777217
#define O_EMB  16777218
#define O_CS   20971522
#define O_W    20979714

#define SMEM_BYTES ((4*STAGE_F + 128 + 128 + 128) * 4)

// ------------------------------- scratch -----------------------------------
__device__ float  g_Ap[(size_t)NUM_IN * KP];    // 192 MB
__device__ float  g_Bp[(size_t)NUM_CODE * KP];  // 48 MB
__device__ float  g_bnorm[NUM_CODE];
__device__ float  g_cand_val[NCHUNK][NUM_IN];
__device__ int    g_cand_idx[NCHUNK][NUM_IN];
__device__ int    g_best[NUM_IN];
__device__ float  g_counts[NUM_CODE];
__device__ double g_loss_sum;

// ------------------------------- helpers -----------------------------------
__device__ __forceinline__ float f2tf32(float x) {
    unsigned u;
    asm("cvt.rna.tf32.f32 %0, %1;" : "=r"(u) : "f"(x));
    return __uint_as_float(u);
}

__device__ __forceinline__ unsigned smem_u32(const void* p) {
    return (unsigned)__cvta_generic_to_shared(p);
}

__device__ __forceinline__ void cp16(unsigned s, const void* g) {
    asm volatile("cp.async.cg.shared.global [%0], [%1], 16;\n" :: "r"(s), "l"(g) : "memory");
}
__device__ __forceinline__ void cp_commit() {
    asm volatile("cp.async.commit_group;\n" ::: "memory");
}
template <int N>
__device__ __forceinline__ void cp_wait() {
    asm volatile("cp.async.wait_group %0;\n" :: "n"(N) : "memory");
}

__device__ __forceinline__ void mma_tf32(float* d, const unsigned* a, const unsigned* b) {
    asm volatile(
        "mma.sync.aligned.m16n8k8.row.col.f32.tf32.tf32.f32 "
        "{%0,%1,%2,%3}, {%4,%5,%6,%7}, {%8,%9}, {%0,%1,%2,%3};\n"
        : "+f"(d[0]), "+f"(d[1]), "+f"(d[2]), "+f"(d[3])
        : "r"(a[0]), "r"(a[1]), "r"(a[2]), "r"(a[3]), "r"(b[0]), "r"(b[1]));
}

// ------------------------------ small kernels -------------------------------
__global__ void k_zero() {
    int i = blockIdx.x * blockDim.x + threadIdx.x;
    if (i < NUM_CODE) g_counts[i] = 0.0f;
    if (i == 0) g_loss_sum = 0.0;
}

__global__ void k_init_w(const float* __restrict__ ema_w, float* __restrict__ out) {
    for (long i = (long)blockIdx.x * blockDim.x + threadIdx.x;
         i < (long)NUM_CODE * DIM; i += (long)gridDim.x * blockDim.x)
        out[O_W + i] = 0.99f * ema_w[i];
}

__global__ void k_prep_a(const float* __restrict__ X) {
    for (long i = (long)blockIdx.x * blockDim.x + threadIdx.x;
         i < (long)NUM_IN * DIM; i += (long)gridDim.x * blockDim.x) {
        int m = (int)(i >> 9);
        int j = (int)(i & 511);
        float v = X[i];
        float hi = f2tf32(v);
        float lo = v - hi;
        float* row = g_Ap + (size_t)m * KP;
        row[j]        = hi;   // seg0 pairs with B_hi
        row[512 + j]  = hi;   // seg1 pairs with B_lo
        row[1024 + j] = lo;   // seg2 pairs with B_hi
    }
}

__global__ void k_prep_b(const float* __restrict__ E) {
    int k = blockIdx.x;
    int t = threadIdx.x;           // 128 threads
    const float* er = E + (size_t)k * DIM;
    float* br = g_Bp + (size_t)k * KP;
    float s = 0.0f;
    for (int j = t; j < DIM; j += 128) {
        float v = er[j];
        float hi = f2tf32(v);
        float lo = v - hi;
        br[j]        = hi;
        br[512 + j]  = lo;
        br[1024 + j] = hi;
        s += v * v;
    }
    // block reduce (4 warps)
    for (int o = 16; o > 0; o >>= 1) s += __shfl_down_sync(0xffffffffu, s, o);
    __shared__ float sw[4];
    if ((t & 31) == 0) sw[t >> 5] = s;
    __syncthreads();
    if (t == 0) g_bnorm[k] = sw[0] + sw[1] + sw[2] + sw[3];
}

// ------------------------------ main GEMM+argmin ----------------------------
__device__ __forceinline__ void load_stage(float* As, float* Bs,
                                           const float* Ag, const float* Bg,
                                           int kbase, int tid) {
#pragma unroll
    for (int i = 0; i < 4; i++) {
        int l = tid + 256 * i;
        int r = l >> 3, f = l & 7;
        cp16(smem_u32(As + r * SROW + f * 4), Ag + (size_t)r * KP + kbase + f * 4);
    }
#pragma unroll
    for (int i = 0; i < 4; i++) {
        int l = tid + 256 * i;
        int r = l >> 3, f = l & 7;
        cp16(smem_u32(Bs + r * SROW + f * 4), Bg + (size_t)r * KP + kbase + f * 4);
    }
}

extern __shared__ float smem[];

__global__ void __launch_bounds__(256, 2) k_argmin_gemm() {
    float* As0   = smem;                    // 2 stages of A
    float* Bs0   = smem + 2 * STAGE_F;      // 2 stages of B
    float* sbias = smem + 4 * STAGE_F;      // 128
    float* rval  = sbias + 128;             // 128
    int*   ridx  = (int*)(rval + 128);      // 128

    const int tid   = threadIdx.x;
    const int lane  = tid & 31;
    const int warp  = tid >> 5;
    const int warpM = warp & 3;   // 0..3
    const int warpN = warp >> 2;  // 0..1
    const int g     = lane >> 2;  // 0..7
    const int q     = lane & 3;   // 0..3

    const int chunk = blockIdx.x;  // 0..3
    const int mtile = blockIdx.y;  // 0..255

    const float* Apanel = g_Ap + (size_t)mtile * BM * KP;

    float bestv[4];
    int   besti[4];
#pragma unroll
    for (int s = 0; s < 4; s++) { bestv[s] = FLT_MAX; besti[s] = 0x7fffffff; }

    for (int nt = 0; nt < NTILES; ++nt) {
        const int code0 = chunk * CODES_PER_CHUNK + nt * BN;
        const float* Bpanel = g_Bp + (size_t)code0 * KP;

        if (tid < 128) sbias[tid] = g_bnorm[code0 + tid];

        float acc[2][8][4];
#pragma unroll
        for (int m = 0; m < 2; m++)
#pragma unroll
            for (int j = 0; j < 8; j++)
#pragma unroll
                for (int c = 0; c < 4; c++) acc[m][j][c] = 0.0f;

        // prime pipeline
        load_stage(As0, Bs0 + 0, Apanel, Bpanel, 0, tid);
        // note: Bs0 base already offset; stage 0 of B is Bs0[0..STAGE_F)
        cp_commit();

        for (int ks = 0; ks < KSTAGES; ++ks) {
            const int buf = ks & 1;
            if (ks + 1 < KSTAGES) {
                load_stage(As0 + (buf ^ 1) * STAGE_F, Bs0 + (buf ^ 1) * STAGE_F,
                           Apanel, Bpanel, (ks + 1) * BK, tid);
                cp_commit();
                cp_wait<1>();
            } else {
                cp_wait<0>();
            }
            __syncthreads();

            const float* As = As0 + buf * STAGE_F;
            const float* Bs = Bs0 + buf * STAGE_F;
            const float* ApT = As + (warpM * 32 + g) * SROW + q;
            const float* BpT = Bs + (warpN * 64 + g) * SROW + q;

#pragma unroll
            for (int kk = 0; kk < 4; ++kk) {
                const int ko = kk * 8;
                unsigned a[2][4], b[8][2];
#pragma unroll
                for (int m = 0; m < 2; m++) {
                    const float* p = ApT + m * 16 * SROW + ko;
                    a[m][0] = __float_as_uint(p[0]);
                    a[m][1] = __float_as_uint(p[8 * SROW]);
                    a[m][2] = __float_as_uint(p[4]);
                    a[m][3] = __float_as_uint(p[8 * SROW + 4]);
                }
#pragma unroll
                for (int j = 0; j < 8; j++) {
                    const float* p = BpT + j * 8 * SROW + ko;
                    b[j][0] = __float_as_uint(p[0]);
                    b[j][1] = __float_as_uint(p[4]);
                }
#pragma unroll
                for (int m = 0; m < 2; m++)
#pragma unroll
                    for (int j = 0; j < 8; j++)
                        mma_tf32(acc[m][j], a[m], b[j]);
            }
            __syncthreads();
        }

        // ---- epilogue: scores = bias - 2*dot, running argmin ----
        const int codeg0 = code0;  // global code id base of this 128-wide tile
#pragma unroll
        for (int m = 0; m < 2; m++) {
#pragma unroll
            for (int half = 0; half < 2; half++) {
                const int slot = m * 2 + half;
                float v = FLT_MAX;
                int   vi = 0x7fffffff;
#pragma unroll
                for (int j = 0; j < 8; j++) {
                    const int colb = warpN * 64 + j * 8 + 2 * q;
                    const float s0 = sbias[colb]     - 2.0f * acc[m][j][half * 2 + 0];
                    const float s1 = sbias[colb + 1] - 2.0f * acc[m][j][half * 2 + 1];
                    const int c0 = codeg0 + colb;
                    if (s0 < v || (s0 == v && c0 < vi))     { v = s0; vi = c0; }
                    if (s1 < v || (s1 == v && c0 + 1 < vi)) { v = s1; vi = c0 + 1; }
                }
                // quad reduce (lanes sharing rows, cols partitioned by q)
#pragma unroll
                for (int off = 1; off < 4; off <<= 1) {
                    float ov = __shfl_xor_sync(0xffffffffu, v, off);
                    int   oi = __shfl_xor_sync(0xffffffffu, vi, off);
                    if (ov < v || (ov == v && oi < vi)) { v = ov; vi = oi; }
                }
                if (v < bestv[slot] || (v == bestv[slot] && vi < besti[slot])) {
                    bestv[slot] = v; besti[slot] = vi;
                }
            }
        }
        __syncthreads();  // protect sbias before next tile rewrites it
    }

    // ---- cross-warp (warpN pair) combine and write candidates ----
    if (warpN == 1 && q == 0) {
#pragma unroll
        for (int s = 0; s < 4; s++) {
            const int m = s >> 1, half = s & 1;
            const int row = warpM * 32 + m * 16 + half * 8 + g;
            rval[row] = bestv[s];
            ridx[row] = besti[s];
        }
    }
    __syncthreads();
    if (warpN == 0 && q == 0) {
#pragma unroll
        for (int s = 0; s < 4; s++) {
            const int m = s >> 1, half = s & 1;
            const int row = warpM * 32 + m * 16 + half * 8 + g;
            float v = bestv[s]; int vi = besti[s];
            float ov = rval[row]; int oi = ridx[row];
            if (ov < v || (ov == v && oi < vi)) { v = ov; vi = oi; }
            g_cand_val[chunk][mtile * 128 + row] = v;
            g_cand_idx[chunk][mtile * 128 + row] = vi;
        }
    }
}

__global__ void k_combine() {
    int r = blockIdx.x * blockDim.x + threadIdx.x;
    if (r >= NUM_IN) return;
    float v = g_cand_val[0][r];
    int vi = g_cand_idx[0][r];
#pragma unroll
    for (int c = 1; c < NCHUNK; c++) {
        float ov = g_cand_val[c][r];
        int oi = g_cand_idx[c][r];
        if (ov < v || (ov == v && oi < vi)) { v = ov; vi = oi; }
    }
    g_best[r] = vi;
}

// ----------------------- gather + scatter (EMA stats) -----------------------
__global__ void k_gather(const float* __restrict__ X, const float* __restrict__ E,
                         float* __restrict__ out) {
    const int row = blockIdx.x;
    const int t = threadIdx.x;  // 128 threads, one float4 each (512 floats/row)
    const int k = g_best[row];

    const float4* ev = (const float4*)(E + (size_t)k * DIM);
    const float4* xv = (const float4*)(X + (size_t)row * DIM);
    float4* qv = (float4*)(out + O_Q + (size_t)row * DIM);
    float* wv = out + O_W + (size_t)k * DIM;

    float4 e4 = __ldg(ev + t);
    float4 x4 = __ldg(xv + t);
    qv[t] = e4;  // quantized_st == quantized numerically

    float dx = e4.x - x4.x, dy = e4.y - x4.y, dz = e4.z - x4.z, dw = e4.w - x4.w;
    float ls = dx * dx + dy * dy + dz * dz + dw * dw;

    atomicAdd(wv + 4 * t + 0, 0.01f * x4.x);
    atomicAdd(wv + 4 * t + 1, 0.01f * x4.y);
    atomicAdd(wv + 4 * t + 2, 0.01f * x4.z);
    atomicAdd(wv + 4 * t + 3, 0.01f * x4.w);

    for (int o = 16; o > 0; o >>= 1) ls += __shfl_down_sync(0xffffffffu, ls, o);
    __shared__ float sred[4];
    if ((t & 31) == 0) sred[t >> 5] = ls;
    __syncthreads();
    if (t == 0) {
        float tot = sred[0] + sred[1] + sred[2] + sred[3];
        atomicAdd(&g_loss_sum, (double)tot);
        atomicAdd(&g_counts[k], 1.0f);
    }
}

// ----------------------------- finalize -------------------------------------
__global__ void k_finalize(const float* __restrict__ cs_in, float* __restrict__ out) {
    __shared__ float  spre[NUM_CODE];  // 32 KB
    __shared__ double snd[256];
    __shared__ float  shd[256];
    const int t = threadIdx.x;  // 256
    double nl = 0.0;
    float hl = 0.0f;
    for (int k = t; k < NUM_CODE; k += 256) {
        float c = g_counts[k];
        float pre = 0.99f * cs_in[k] + 0.01f * c;
        spre[k] = pre;
        nl += (double)pre;
        float p = c * (1.0f / 32768.0f);
        hl += p * logf(p + 1e-10f);
    }
    snd[t] = nl; shd[t] = hl;
    __syncthreads();
    for (int s = 128; s > 0; s >>= 1) {
        if (t < s) { snd[t] += snd[t + s]; shd[t] += shd[t + s]; }
        __syncthreads();
    }
    const float n = (float)snd[0];
    const float denom = n + (float)NUM_CODE * 1e-5f;
    for (int k = t; k < NUM_CODE; k += 256)
        out[O_CS + k] = (spre[k] + 1e-5f) / denom * n;
    if (t == 0) {
        out[O_LOSS] = 0.25f * (float)(g_loss_sum / 16777216.0);
        out[O_PERP] = expf(-shd[0]);
    }
}

__global__ void k_newemb(float* __restrict__ out) {
    for (long i = (long)blockIdx.x * blockDim.x + threadIdx.x;
         i < (long)NUM_CODE * DIM; i += (long)gridDim.x * blockDim.x)
        out[O_EMB + i] = out[O_W + i] / out[O_CS + (i >> 9)];
}

// ------------------------------- launch --------------------------------------
extern "C" void kernel_launch(void* const* d_in, const int* in_sizes, int n_in,
                              void* d_out, int out_size) {
    const float* X  = (const float*)d_in[0];  // inputs          [32768,512]
    const float* E  = (const float*)d_in[1];  // embedding       [8192,512]
    const float* CS = (const float*)d_in[2];  // ema_cluster_size[8192]
    const float* W  = (const float*)d_in[3];  // ema_w           [8192,512]
    float* out = (float*)d_out;

    cudaFuncSetAttribute(k_argmin_gemm, cudaFuncAttributeMaxDynamicSharedMemorySize,
                         SMEM_BYTES);

    k_zero<<<(NUM_CODE + 255) / 256, 256>>>();
    k_init_w<<<4096, 256>>>(W, out);
    k_prep_b<<<NUM_CODE, 128>>>(E);
    k_prep_a<<<8192, 256>>>(X);
    k_argmin_gemm<<<dim3(NCHUNK, NUM_IN / BM), 256, SMEM_BYTES>>>();
    k_combine<<<NUM_IN / 256, 256>>>();
    k_gather<<<NUM_IN, 128>>>(X, E, out);
    k_finalize<<<1, 256>>>(CS, out);
    k_newemb<<<4096, 256>>>(out);
}